// round 7
// baseline (speedup 1.0000x reference)
#include <cuda_runtime.h>
#include <cuda_fp16.h>
#include <cstdint>
#include <mma.h>
using namespace nvcuda;

// Problem dims (fixed by the dataset)
#define B_    2
#define S_    2048
#define D_    2048
#define H_    16
#define DH_   128
#define DFF_  8192
#define DHP_  160           // 129-dim lorentz q/k padded to multiple of 32
#define BH_   32            // B_*H_
#define NROWS 4096          // B_*S_

// wmma 128x128 path (scores / PV)
#define STAGE_H 5120
#define NSTAGE  3
#define SMEM_BYTES (NSTAGE * STAGE_H * 2 * 2)   // 61440 B

// wmma 256x128 path (dense GEMMs)
#define G2_AST   20480      // A stage: 256 rows x 40 halves x 2B
#define G2_BST   10240      // B stage: 128 rows x 40 halves x 2B
#define G2_STAGE (G2_AST + G2_BST)               // 30720
#define G2_SMEM  (3 * G2_STAGE)                  // 92160

// ---------------- scratch (static device globals; no allocs) ----------------
__device__ float  g_v  [(size_t)NROWS*D_];
__device__ __half g_u1 [(size_t)NROWS*D_];
__device__ __half g_wq [(size_t)D_*D_];      // transposed [N,K] fp16
__device__ __half g_wk [(size_t)D_*D_];
__device__ __half g_wv [(size_t)D_*D_];
__device__ __half g_wo [(size_t)D_*D_];
__device__ __half g_w1 [(size_t)D_*DFF_];    // [8192, 2048]
__device__ __half g_w2 [(size_t)DFF_*D_];    // [2048, 8192]
__device__ __half g_q  [(size_t)NROWS*D_];
__device__ __half g_kk [(size_t)NROWS*D_];
__device__ __half g_vr [(size_t)NROWS*D_];
__device__ __half g_qh [(size_t)BH_*S_*DHP_];
__device__ __half g_kh [(size_t)BH_*S_*DHP_];
__device__ __half g_vh [(size_t)BH_*S_*DH_];
__device__ __half g_sc [(size_t)BH_*S_*S_];
__device__ __half g_pm [(size_t)BH_*S_*S_];
__device__ __half g_ao [(size_t)NROWS*D_];
__device__ float  g_u2 [(size_t)NROWS*D_];
__device__ __half g_hid[(size_t)NROWS*DFF_];
__device__ float  g_uf [(size_t)NROWS*D_];

// ---------------- cp.async helpers ----------------
__device__ __forceinline__ void cp16(void* dst, const void* src){
  unsigned d = (unsigned)__cvta_generic_to_shared(dst);
  asm volatile("cp.async.cg.shared.global [%0], [%1], 16;" :: "r"(d), "l"(src));
}
__device__ __forceinline__ void cp_commit(){ asm volatile("cp.async.commit_group;"); }
template<int N> __device__ __forceinline__ void cp_wait(){
  asm volatile("cp.async.wait_group %0;" :: "n"(N));
}

// ---------------- reductions ----------------
__device__ __forceinline__ float warpSum(float v){
#pragma unroll
  for (int o=16;o>0;o>>=1) v += __shfl_xor_sync(0xffffffffu, v, o);
  return v;
}
__device__ __forceinline__ float warpMax(float v){
#pragma unroll
  for (int o=16;o>0;o>>=1) v = fmaxf(v, __shfl_xor_sync(0xffffffffu, v, o));
  return v;
}
__device__ float blockSum(float v){
  __shared__ float sh[9];
  int lane = threadIdx.x & 31, wid = threadIdx.x >> 5;
  v = warpSum(v);
  __syncthreads();
  if (lane == 0) sh[wid] = v;
  __syncthreads();
  if (wid == 0){
    float r = (lane < 8) ? sh[lane] : 0.f;
    r = warpSum(r);
    if (lane == 0) sh[8] = r;
  }
  __syncthreads();
  return sh[8];
}
__device__ float blockMax(float v){
  __shared__ float sm[9];
  int lane = threadIdx.x & 31, wid = threadIdx.x >> 5;
  v = warpMax(v);
  __syncthreads();
  if (lane == 0) sm[wid] = v;
  __syncthreads();
  if (wid == 0){
    float r = (lane < 8) ? sm[lane] : -3.0e38f;
    r = warpMax(r);
    if (lane == 0) sm[8] = r;
  }
  __syncthreads();
  return sm[8];
}

// ---------------- small kernels ----------------
// fused transpose + fp32->fp16: src [K,N] -> dst [N,K]
__global__ void f2hT(const float* __restrict__ src, __half* __restrict__ dst, int K, int N){
  __shared__ float tile[32][33];
  int k0 = blockIdx.y*32, n0 = blockIdx.x*32;
  int tx = threadIdx.x & 31, ty = threadIdx.x >> 5;   // 256 threads, ty 0..7
#pragma unroll
  for (int i=0;i<32;i+=8)
    tile[ty+i][tx] = src[(size_t)(k0+ty+i)*N + n0+tx];
  __syncthreads();
#pragma unroll
  for (int i=0;i<32;i+=8)
    dst[(size_t)(n0+ty+i)*K + k0+tx] = __float2half(tile[tx][ty+i]);
}

// per-row: v = log_map(x); u1 = scale1 * v / rms(v)
__global__ void prep1(const float* __restrict__ x, const float* __restrict__ scale1){
  int row = blockIdx.x, t = threadIdx.x;
  const float* xr = x + (size_t)row*2049 + 1;
  float xi[8]; float ss = 0.f;
#pragma unroll
  for (int j=0;j<8;j++){ xi[j] = xr[t + j*256]; ss += xi[j]*xi[j]; }
  ss = blockSum(ss);
  float n = sqrtf(ss);
  float f = (n < 1e-6f) ? (1.0f - n*n/6.0f) : (asinhf(n) / fmaxf(n, 1e-12f));
  float rinv = 1.0f / sqrtf(f*f*ss*(1.0f/D_) + 1e-6f);
#pragma unroll
  for (int j=0;j<8;j++){
    int c = t + j*256;
    float v = f * xi[j];
    g_v [(size_t)row*D_ + c] = v;
    g_u1[(size_t)row*D_ + c] = __float2half(scale1[c] * v * rinv);
  }
}

// per (b,s): lift q,k to lorentz, copy v head-major
__global__ void headprep(const float* __restrict__ headK){
  int r = blockIdx.x;
  int b = r >> 11, s = r & 2047;
  int wid = threadIdx.x >> 5, lane = threadIdx.x & 31;
#pragma unroll
  for (int rep=0; rep<2; rep++){
    int h = wid*2 + rep;
    int z = b*H_ + h;
    size_t ib = (size_t)r*D_ + (size_t)h*DH_;
    size_t qb = ((size_t)z*S_ + s)*DHP_;
    size_t vb = ((size_t)z*S_ + s)*DH_;
    float Kh = headK[h];
    float sK = sqrtf(-Kh);
    float inv_negK = -1.0f / Kh;
    float qv[4], kv[4]; float ssq = 0.f, ssk = 0.f;
#pragma unroll
    for (int j=0;j<4;j++){
      qv[j] = __half2float(g_q [ib + lane*4 + j]); ssq += qv[j]*qv[j];
      kv[j] = __half2float(g_kk[ib + lane*4 + j]); ssk += kv[j]*kv[j];
      g_vh[vb + lane*4 + j] = g_vr[ib + lane*4 + j];
    }
    ssq = warpSum(ssq); ssk = warpSum(ssk);
    float aq = sK * sqrtf(ssq);
    float sq = (aq < 1e-6f) ? (1.0f + aq*aq/6.0f) : (sinhf(aq)/aq);
    float ak = sK * sqrtf(ssk);
    float sk = (ak < 1e-6f) ? (1.0f + ak*ak/6.0f) : (sinhf(ak)/ak);
#pragma unroll
    for (int j=0;j<4;j++){
      g_qh[qb + lane*4 + j] = __float2half(sq * qv[j]);
      g_kh[qb + lane*4 + j] = __float2half(sk * kv[j]);
    }
    float x0q = sqrtf(inv_negK + sq*sq*ssq);
    float x0k = sqrtf(inv_negK + sk*sk*ssk);
    g_qh[qb + 128 + lane] = (lane==0) ? __float2half(-x0q) : __float2half(0.f);
    g_kh[qb + 128 + lane] = (lane==0) ? __float2half( x0k) : __float2half(0.f);
  }
}

// causal-aware softmax
__global__ void softmaxk(){
  int q = blockIdx.x, z = blockIdx.y, t = threadIdx.x;
  size_t base = ((size_t)z*S_ + q)*S_;
  int nlim = (q & ~127) + 128;
  float v[8]; float mx = -3.0e38f;
#pragma unroll
  for (int j=0;j<8;j++){
    int c = t + j*256;
    bool ok = c < nlim;
    v[j] = ok ? __half2float(g_sc[base + c]) : -1.0e30f;
    mx = fmaxf(mx, v[j]);
  }
  mx = blockMax(mx);
  float s = 0.f;
#pragma unroll
  for (int j=0;j<8;j++){ v[j] = __expf(v[j] - mx); s += v[j]; }
  s = blockSum(s);
  float inv = 1.0f / s;
#pragma unroll
  for (int j=0;j<8;j++){
    int c = t + j*256;
    if (c < nlim) g_pm[base + c] = __float2half(v[j] * inv);
  }
}

// per-row: u1 = scale2 * u2 / rms(u2)
__global__ void prep2(const float* __restrict__ scale2){
  int row = blockIdx.x, t = threadIdx.x;
  float u[8]; float ss = 0.f;
#pragma unroll
  for (int j=0;j<8;j++){ u[j] = g_u2[(size_t)row*D_ + t + j*256]; ss += u[j]*u[j]; }
  ss = blockSum(ss);
  float rinv = 1.0f / sqrtf(ss*(1.0f/D_) + 1e-6f);
#pragma unroll
  for (int j=0;j<8;j++){
    int c = t + j*256;
    g_u1[(size_t)row*D_ + c] = __float2half(scale2[c] * u[j] * rinv);
  }
}

// per-row: out = exp_map(uf), K=-1
__global__ void finalk(float* __restrict__ out){
  int row = blockIdx.x, t = threadIdx.x;
  float u[8]; float ss = 0.f;
#pragma unroll
  for (int j=0;j<8;j++){ u[j] = g_uf[(size_t)row*D_ + t + j*256]; ss += u[j]*u[j]; }
  ss = blockSum(ss);
  float n = sqrtf(ss);
  float sinc = (n < 1e-6f) ? (1.0f + n*n/6.0f) : (sinhf(n)/n);
  float* o = out + (size_t)row*2049;
  if (t == 0) o[0] = sqrtf(1.0f + sinc*sinc*ss);
#pragma unroll
  for (int j=0;j<8;j++) o[1 + t + j*256] = sinc * u[j];
}

enum { M_HALF = 0, M_SCORES = 1, M_PV = 2, M_WO = 3, M_GELU = 4, M_W2 = 5 };

// ============ 256x128 dense GEMM: C[M,N] = A[M,K] @ Bt[N,K]^T ============
// 8 warps, each computes 64x64. 3-stage cp.async. Modes: HALF / WO / GELU / W2.
template<int MODE>
__global__ __launch_bounds__(256, 1) void gemm256(
    const __half* __restrict__ A, const __half* __restrict__ Bt,
    void* __restrict__ C, const float* __restrict__ aux,
    int K, int ldc)
{
  extern __shared__ __half smem[];
  const int rm0 = blockIdx.y * 256;
  const int cn0 = blockIdx.x * 128;
  const int tid = threadIdx.x;
  const int wid = tid >> 5, lane = tid & 31;
  const int wm = wid >> 1, wn = wid & 1;       // 4 x 2 warp grid, 64x64 each
  const int KT = K >> 5;

  // load coords
  const int ar0 = tid >> 2,  ac0 = (tid & 3) * 8;    // A: 4 its x 64 rows

  auto loadTile = [&](int kt, int buf){
    int k0 = kt << 5;
    __half* as = smem + buf*(G2_STAGE/2);
    __half* bs = as + G2_AST/2;
#pragma unroll
    for (int it=0; it<4; it++){
      int r = ar0 + it*64;
      cp16(&as[r*40 + ac0], A + (size_t)(rm0 + r)*K + k0 + ac0);
    }
    // B stored [n][k] (128 x 32, stride 40); col_major fragment gives B^T
#pragma unroll
    for (int it=0; it<2; it++){
      int r = (tid >> 2) + it*64;                   // n index 0..127
      int c8 = (tid & 3) * 8;                       // k offset
      cp16(&bs[r*40 + c8], Bt + (size_t)(cn0 + r)*K + k0 + c8);
    }
  };

  wmma::fragment<wmma::accumulator,16,16,16,float> fc[4][4];
#pragma unroll
  for (int i=0;i<4;i++)
#pragma unroll
    for (int j=0;j<4;j++) wmma::fill_fragment(fc[i][j], 0.0f);

  loadTile(0, 0); cp_commit();
  if (KT > 1) loadTile(1, 1);
  cp_commit();

  for (int kt = 0; kt < KT; kt++){
    cp_wait<1>();
    __syncthreads();
    if (kt + 2 < KT) loadTile(kt+2, (kt+2)%3);
    cp_commit();
    const __half* as = smem + (kt%3)*(G2_STAGE/2);
    const __half* bs = as + G2_AST/2;
#pragma unroll
    for (int kk=0; kk<32; kk+=16){
      wmma::fragment<wmma::matrix_a,16,16,16,__half,wmma::row_major> fa[4];
#pragma unroll
      for (int i=0;i<4;i++)
        wmma::load_matrix_sync(fa[i], &as[(wm*64 + i*16)*40 + kk], 40);
#pragma unroll
      for (int j=0;j<4;j++){
        wmma::fragment<wmma::matrix_b,16,16,16,__half,wmma::col_major> fb;
        wmma::load_matrix_sync(fb, &bs[(wn*64 + j*16)*40 + kk], 40);
#pragma unroll
        for (int i=0;i<4;i++) wmma::mma_sync(fc[i][j], fa[i], fb, fc[i][j]);
      }
    }
  }

  // ---- epilogue: stage 16x16 tiles through shared, vectorized stores ----
  __syncthreads();
  float* Es = reinterpret_cast<float*>(smem);
  float* es = Es + wid*320;
  const int r  = lane >> 1;
  const int ch = (lane & 1) * 8;
#pragma unroll
  for (int mi=0; mi<4; mi++){
#pragma unroll
    for (int nj=0; nj<4; nj++){
      wmma::store_matrix_sync(es, fc[mi][nj], 20, wmma::mem_row_major);
      __syncwarp();
      float4 v0 = *reinterpret_cast<const float4*>(&es[r*20 + ch]);
      float4 v1 = *reinterpret_cast<const float4*>(&es[r*20 + ch + 4]);
      float vals[8] = {v0.x,v0.y,v0.z,v0.w, v1.x,v1.y,v1.z,v1.w};
      int gr = rm0 + wm*64 + mi*16 + r;
      int gc = cn0 + wn*64 + nj*16 + ch;
      if constexpr (MODE == M_HALF || MODE == M_GELU){
        __half h8[8];
#pragma unroll
        for (int e=0;e<8;e++){
          float val = vals[e];
          if constexpr (MODE == M_GELU)
            val = 0.5f*val*(1.0f + erff(val*0.70710678118654752f));
          h8[e] = __float2half(val);
        }
        *reinterpret_cast<int4*>((__half*)C + (size_t)gr*ldc + gc) = *reinterpret_cast<int4*>(h8);
      } else {  // M_WO / M_W2: fp32 out = val + aux
        size_t i2 = (size_t)gr*ldc + gc;
        float4 a0 = *reinterpret_cast<const float4*>(aux + i2);
        float4 a1 = *reinterpret_cast<const float4*>(aux + i2 + 4);
        float4 o0 = make_float4(vals[0]+a0.x, vals[1]+a0.y, vals[2]+a0.z, vals[3]+a0.w);
        float4 o1 = make_float4(vals[4]+a1.x, vals[5]+a1.y, vals[6]+a1.z, vals[7]+a1.w);
        *reinterpret_cast<float4*>((float*)C + i2)     = o0;
        *reinterpret_cast<float4*>((float*)C + i2 + 4) = o1;
      }
      __syncwarp();
    }
  }
}

// ---------------- wmma GEMM 128x128 (scores / PV) ----------------
template<int MODE>
__global__ __launch_bounds__(256) void gemm_k(
    const __half* __restrict__ A, const __half* __restrict__ Bm,
    void* __restrict__ C, const float* __restrict__ aux,
    int M, int N, int K, int lda, int ldb, int ldc,
    long long strA, long long strB, long long strC)
{
  constexpr bool BT = (MODE == M_SCORES);
  extern __shared__ __half smem[];
  __half* As = smem;
  __half* Bs = smem + NSTAGE*STAGE_H;

  const int z = blockIdx.z;
  const int rm0 = blockIdx.y * 128;
  const int cn0 = blockIdx.x * 128;

  if constexpr (MODE == M_SCORES){
    if (cn0 > rm0 + 127) return;
  }
  if constexpr (MODE == M_PV){
    K = min(K, rm0 + 128);
  }

  const __half* Ab = A  + (size_t)z * strA;
  const __half* Bb = Bm + (size_t)z * strB;
  const int tid = threadIdx.x;
  const int wid = tid >> 5, lane = tid & 31;
  const int wm = wid >> 1, wn = wid & 1;
  const int KT = K >> 5;

  const int ar0 = tid >> 2,  ac0 = (tid & 3) * 8;
  const int br0 = tid >> 4,  bc0 = (tid & 15) * 8;
  const int tr0 = tid >> 2,  tc0 = (tid & 3) * 8;

  auto loadTile = [&](int kt, int buf){
    int k0 = kt << 5;
    __half* as = As + buf*STAGE_H;
    __half* bs = Bs + buf*STAGE_H;
#pragma unroll
    for (int it=0; it<2; it++){
      int r = ar0 + it*64;
      cp16(&as[r*40 + ac0], Ab + (size_t)(rm0 + r)*lda + k0 + ac0);
    }
    if constexpr (!BT){
#pragma unroll
      for (int it=0; it<2; it++){
        int r = br0 + it*16;
        cp16(&bs[r*136 + bc0], Bb + (size_t)(k0 + r)*ldb + cn0 + bc0);
      }
    } else {
#pragma unroll
      for (int it=0; it<2; it++){
        int r = tr0 + it*64;
        cp16(&bs[r*40 + tc0], Bb + (size_t)(cn0 + r)*ldb + k0 + tc0);
      }
    }
  };

  wmma::fragment<wmma::accumulator,16,16,16,float> fc[2][4];
#pragma unroll
  for (int i=0;i<2;i++)
#pragma unroll
    for (int j=0;j<4;j++) wmma::fill_fragment(fc[i][j], 0.0f);

  loadTile(0, 0); cp_commit();
  if (KT > 1) loadTile(1, 1);
  cp_commit();

  for (int kt = 0; kt < KT; kt++){
    cp_wait<1>();
    __syncthreads();
    if (kt + 2 < KT) loadTile(kt+2, (kt+2)%3);
    cp_commit();
    const __half* as = As + (kt%3)*STAGE_H;
    const __half* bs = Bs + (kt%3)*STAGE_H;
#pragma unroll
    for (int kk=0; kk<32; kk+=16){
      wmma::fragment<wmma::matrix_a,16,16,16,__half,wmma::row_major> fa[2];
#pragma unroll
      for (int i=0;i<2;i++)
        wmma::load_matrix_sync(fa[i], &as[(wm*32 + i*16)*40 + kk], 40);
      if constexpr (!BT){
#pragma unroll
        for (int j=0;j<4;j++){
          wmma::fragment<wmma::matrix_b,16,16,16,__half,wmma::row_major> fb;
          wmma::load_matrix_sync(fb, &bs[kk*136 + wn*64 + j*16], 136);
#pragma unroll
          for (int i=0;i<2;i++) wmma::mma_sync(fc[i][j], fa[i], fb, fc[i][j]);
        }
      } else {
#pragma unroll
        for (int j=0;j<4;j++){
          wmma::fragment<wmma::matrix_b,16,16,16,__half,wmma::col_major> fb;
          wmma::load_matrix_sync(fb, &bs[(wn*64 + j*16)*40 + kk], 40);
#pragma unroll
          for (int i=0;i<2;i++) wmma::mma_sync(fc[i][j], fa[i], fb, fc[i][j]);
        }
      }
    }
  }

  __syncthreads();
  float* Es = reinterpret_cast<float*>(smem);
  float* es = Es + wid*320;
  const int r  = lane >> 1;
  const int ch = (lane & 1) * 8;
#pragma unroll
  for (int mi=0; mi<2; mi++){
#pragma unroll
    for (int nj=0; nj<4; nj++){
      wmma::store_matrix_sync(es, fc[mi][nj], 20, wmma::mem_row_major);
      __syncwarp();
      float4 v0 = *reinterpret_cast<const float4*>(&es[r*20 + ch]);
      float4 v1 = *reinterpret_cast<const float4*>(&es[r*20 + ch + 4]);
      float vals[8] = {v0.x,v0.y,v0.z,v0.w, v1.x,v1.y,v1.z,v1.w};
      int gr = rm0 + wm*32 + mi*16 + r;
      int gc = cn0 + wn*64 + nj*16 + ch;
      if constexpr (MODE == M_SCORES){
        __half h8[8];
#pragma unroll
        for (int e=0;e<8;e++){
          float val = vals[e] * 0.17677669529663687f;
          if (gc + e > gr) val = -60000.0f;
          h8[e] = __float2half(val);
        }
        *reinterpret_cast<int4*>((__half*)C + (size_t)z*strC + (size_t)gr*ldc + gc) = *reinterpret_cast<int4*>(h8);
      } else if constexpr (MODE == M_PV){
        int b = z >> 4, h = z & 15;
        __half h8[8];
#pragma unroll
        for (int e=0;e<8;e++) h8[e] = __float2half(vals[e]);
        *reinterpret_cast<int4*>((__half*)C + ((size_t)(b*S_ + gr))*D_ + (size_t)h*DH_ + gc) = *reinterpret_cast<int4*>(h8);
      }
      __syncwarp();
    }
  }
}

// ---------------- host ----------------
static void* symaddr(const void* s){
  void* p = nullptr;
  cudaGetSymbolAddress(&p, s);
  return p;
}

extern "C" void kernel_launch(void* const* d_in, const int* in_sizes, int n_in,
                              void* d_out, int out_size) {
  const float* x      = (const float*)d_in[0];
  const float* scale1 = (const float*)d_in[2];
  const float* scale2 = (const float*)d_in[3];
  const float* Wq     = (const float*)d_in[4];
  const float* Wk     = (const float*)d_in[5];
  const float* Wv     = (const float*)d_in[6];
  const float* Wo     = (const float*)d_in[7];
  const float* headK  = (const float*)d_in[8];
  const float* W1     = (const float*)d_in[9];
  const float* W2     = (const float*)d_in[10];

  __half* wq = (__half*)symaddr(g_wq);
  __half* wk = (__half*)symaddr(g_wk);
  __half* wv = (__half*)symaddr(g_wv);
  __half* wo = (__half*)symaddr(g_wo);
  __half* w1 = (__half*)symaddr(g_w1);
  __half* w2 = (__half*)symaddr(g_w2);
  __half* u1 = (__half*)symaddr(g_u1);
  __half* qh = (__half*)symaddr(g_qh);
  __half* kh = (__half*)symaddr(g_kh);
  __half* vh = (__half*)symaddr(g_vh);
  __half* pm = (__half*)symaddr(g_pm);
  __half* ao = (__half*)symaddr(g_ao);
  __half* hid= (__half*)symaddr(g_hid);
  void*   qq = symaddr(g_q);
  void*   kkp= symaddr(g_kk);
  void*   vr = symaddr(g_vr);
  void*   sc = symaddr(g_sc);
  void*   u2 = symaddr(g_u2);
  void*   uf = symaddr(g_uf);
  const float* vlog = (const float*)symaddr(g_v);

  cudaFuncSetAttribute(gemm_k<M_SCORES>, cudaFuncAttributeMaxDynamicSharedMemorySize, SMEM_BYTES);
  cudaFuncSetAttribute(gemm_k<M_PV>,     cudaFuncAttributeMaxDynamicSharedMemorySize, SMEM_BYTES);
  cudaFuncSetAttribute(gemm256<M_HALF>,  cudaFuncAttributeMaxDynamicSharedMemorySize, G2_SMEM);
  cudaFuncSetAttribute(gemm256<M_WO>,    cudaFuncAttributeMaxDynamicSharedMemorySize, G2_SMEM);
  cudaFuncSetAttribute(gemm256<M_GELU>,  cudaFuncAttributeMaxDynamicSharedMemorySize, G2_SMEM);
  cudaFuncSetAttribute(gemm256<M_W2>,    cudaFuncAttributeMaxDynamicSharedMemorySize, G2_SMEM);

  // 1) weight transpose + convert: W [K,N] fp32 -> Wt [N,K] fp16
  f2hT<<<dim3(D_/32,  D_/32),  256>>>(Wq, wq, D_,   D_);
  f2hT<<<dim3(D_/32,  D_/32),  256>>>(Wk, wk, D_,   D_);
  f2hT<<<dim3(D_/32,  D_/32),  256>>>(Wv, wv, D_,   D_);
  f2hT<<<dim3(D_/32,  D_/32),  256>>>(Wo, wo, D_,   D_);
  f2hT<<<dim3(DFF_/32,D_/32),  256>>>(W1, w1, D_,   DFF_);
  f2hT<<<dim3(D_/32,  DFF_/32),256>>>(W2, w2, DFF_, D_);

  // 2) log map + rmsnorm-in-log-space
  prep1<<<NROWS,256>>>(x, scale1);

  // 3) QKV projections (256x128 tiles)
  gemm256<M_HALF><<<dim3(D_/128, NROWS/256), 256, G2_SMEM>>>(u1, wq, qq,  nullptr, D_, D_);
  gemm256<M_HALF><<<dim3(D_/128, NROWS/256), 256, G2_SMEM>>>(u1, wk, kkp, nullptr, D_, D_);
  gemm256<M_HALF><<<dim3(D_/128, NROWS/256), 256, G2_SMEM>>>(u1, wv, vr,  nullptr, D_, D_);

  // 4) lorentz lift
  headprep<<<NROWS,256>>>(headK);

  // 5) scores (wmma 128x128, masked tiles skipped)
  gemm_k<M_SCORES><<<dim3(16,16,BH_),256,SMEM_BYTES>>>(qh, kh, sc, nullptr,
      S_, S_, DHP_, DHP_, DHP_, S_,
      (long long)S_*DHP_, (long long)S_*DHP_, (long long)S_*S_);

  // 6) softmax
  softmaxk<<<dim3(S_,BH_),256>>>();

  // 7) P @ V (wmma 128x128, causal K cap)
  gemm_k<M_PV><<<dim3(1,16,BH_),256,SMEM_BYTES>>>(pm, vh, ao, nullptr,
      S_, DH_, S_, S_, DH_, DH_,
      (long long)S_*S_, (long long)S_*DH_, 0);

  // 8) attn @ Wo + residual(v) -> u2 (256x128)
  gemm256<M_WO><<<dim3(D_/128, NROWS/256), 256, G2_SMEM>>>(ao, wo, u2, vlog, D_, D_);

  // 9) rmsnorm in log space
  prep2<<<NROWS,256>>>(scale2);

  // 10) FFN up + GELU (256x128)
  gemm256<M_GELU><<<dim3(DFF_/128, NROWS/256), 256, G2_SMEM>>>(u1, w1, hid, nullptr, D_, DFF_);

  // 11) FFN down + residual(u2) -> uf (256x128)
  gemm256<M_W2><<<dim3(D_/128, NROWS/256), 256, G2_SMEM>>>(hid, w2, uf, (const float*)u2, DFF_, D_);

  // 12) final exp map
  finalk<<<NROWS,256>>>((float*)d_out);
}

// round 8
// speedup vs baseline: 1.0748x; 1.0748x over previous
#include <cuda_runtime.h>
#include <cuda_fp16.h>
#include <cstdint>
#include <mma.h>
using namespace nvcuda;

// Problem dims (fixed by the dataset)
#define B_    2
#define S_    2048
#define D_    2048
#define H_    16
#define DH_   128
#define DFF_  8192
#define DHP_  160           // 129-dim lorentz q/k padded to multiple of 32
#define BH_   32            // B_*H_
#define NROWS 4096          // B_*S_
#define DQKV  6144          // 3*D_

// wmma 128x128 8-warp path (scores / PV)
#define STAGE_H 5120
#define NSTAGE  3
#define SMEM_BYTES (NSTAGE * STAGE_H * 2 * 2)   // 61440 B

// 4-warp 128x128 dense path: per stage A(128x32,str40) + B(128x32,str40)
#define S4_STAGE_H 10240                         // halves per stage
#define S4_SMEM    (3 * S4_STAGE_H * 2)          // 61440 B

// ---------------- scratch (static device globals; no allocs) ----------------
__device__ float  g_v  [(size_t)NROWS*D_];
__device__ __half g_u1 [(size_t)NROWS*D_];
__device__ __half g_wqkv[(size_t)DQKV*D_];   // packed transposed [6144,2048] fp16
__device__ __half g_wo [(size_t)D_*D_];
__device__ __half g_w1 [(size_t)D_*DFF_];    // [8192, 2048]
__device__ __half g_w2 [(size_t)DFF_*D_];    // [2048, 8192]
__device__ __half g_qkv[(size_t)NROWS*DQKV]; // packed QKV output [row, 6144]
__device__ __half g_qh [(size_t)BH_*S_*DHP_];
__device__ __half g_kh [(size_t)BH_*S_*DHP_];
__device__ __half g_vh [(size_t)BH_*S_*DH_];
__device__ __half g_sc [(size_t)BH_*S_*S_];
__device__ __half g_pm [(size_t)BH_*S_*S_];
__device__ __half g_ao [(size_t)NROWS*D_];
__device__ float  g_u2 [(size_t)NROWS*D_];
__device__ __half g_hid[(size_t)NROWS*DFF_];
__device__ float  g_uf [(size_t)NROWS*D_];

// ---------------- cp.async helpers ----------------
__device__ __forceinline__ void cp16(void* dst, const void* src){
  unsigned d = (unsigned)__cvta_generic_to_shared(dst);
  asm volatile("cp.async.cg.shared.global [%0], [%1], 16;" :: "r"(d), "l"(src));
}
__device__ __forceinline__ void cp_commit(){ asm volatile("cp.async.commit_group;"); }
template<int N> __device__ __forceinline__ void cp_wait(){
  asm volatile("cp.async.wait_group %0;" :: "n"(N));
}

// ---------------- reductions ----------------
__device__ __forceinline__ float warpSum(float v){
#pragma unroll
  for (int o=16;o>0;o>>=1) v += __shfl_xor_sync(0xffffffffu, v, o);
  return v;
}
__device__ __forceinline__ float warpMax(float v){
#pragma unroll
  for (int o=16;o>0;o>>=1) v = fmaxf(v, __shfl_xor_sync(0xffffffffu, v, o));
  return v;
}
__device__ float blockSum(float v){
  __shared__ float sh[9];
  int lane = threadIdx.x & 31, wid = threadIdx.x >> 5;
  v = warpSum(v);
  __syncthreads();
  if (lane == 0) sh[wid] = v;
  __syncthreads();
  if (wid == 0){
    float r = (lane < 8) ? sh[lane] : 0.f;
    r = warpSum(r);
    if (lane == 0) sh[8] = r;
  }
  __syncthreads();
  return sh[8];
}
__device__ float blockMax(float v){
  __shared__ float sm[9];
  int lane = threadIdx.x & 31, wid = threadIdx.x >> 5;
  v = warpMax(v);
  __syncthreads();
  if (lane == 0) sm[wid] = v;
  __syncthreads();
  if (wid == 0){
    float r = (lane < 8) ? sm[lane] : -3.0e38f;
    r = warpMax(r);
    if (lane == 0) sm[8] = r;
  }
  __syncthreads();
  return sm[8];
}

// ---------------- small kernels ----------------
// fused transpose + fp32->fp16: src [K,N] -> dst [N,K]
__global__ void f2hT(const float* __restrict__ src, __half* __restrict__ dst, int K, int N){
  __shared__ float tile[32][33];
  int k0 = blockIdx.y*32, n0 = blockIdx.x*32;
  int tx = threadIdx.x & 31, ty = threadIdx.x >> 5;   // 256 threads, ty 0..7
#pragma unroll
  for (int i=0;i<32;i+=8)
    tile[ty+i][tx] = src[(size_t)(k0+ty+i)*N + n0+tx];
  __syncthreads();
#pragma unroll
  for (int i=0;i<32;i+=8)
    dst[(size_t)(n0+ty+i)*K + k0+tx] = __float2half(tile[tx][ty+i]);
}

// per-row: v = log_map(x); u1 = scale1 * v / rms(v)
__global__ void prep1(const float* __restrict__ x, const float* __restrict__ scale1){
  int row = blockIdx.x, t = threadIdx.x;
  const float* xr = x + (size_t)row*2049 + 1;
  float xi[8]; float ss = 0.f;
#pragma unroll
  for (int j=0;j<8;j++){ xi[j] = xr[t + j*256]; ss += xi[j]*xi[j]; }
  ss = blockSum(ss);
  float n = sqrtf(ss);
  float f = (n < 1e-6f) ? (1.0f - n*n/6.0f) : (asinhf(n) / fmaxf(n, 1e-12f));
  float rinv = 1.0f / sqrtf(f*f*ss*(1.0f/D_) + 1e-6f);
#pragma unroll
  for (int j=0;j<8;j++){
    int c = t + j*256;
    float v = f * xi[j];
    g_v [(size_t)row*D_ + c] = v;
    g_u1[(size_t)row*D_ + c] = __float2half(scale1[c] * v * rinv);
  }
}

// per (b,s): lift q,k to lorentz, copy v head-major (reads packed QKV)
__global__ void headprep(const float* __restrict__ headK){
  int r = blockIdx.x;
  int b = r >> 11, s = r & 2047;
  int wid = threadIdx.x >> 5, lane = threadIdx.x & 31;
#pragma unroll
  for (int rep=0; rep<2; rep++){
    int h = wid*2 + rep;
    int z = b*H_ + h;
    size_t ib = (size_t)r*DQKV + (size_t)h*DH_;
    size_t qb = ((size_t)z*S_ + s)*DHP_;
    size_t vb = ((size_t)z*S_ + s)*DH_;
    float Kh = headK[h];
    float sK = sqrtf(-Kh);
    float inv_negK = -1.0f / Kh;
    float qv[4], kv[4]; float ssq = 0.f, ssk = 0.f;
#pragma unroll
    for (int j=0;j<4;j++){
      qv[j] = __half2float(g_qkv[ib + lane*4 + j]);            ssq += qv[j]*qv[j];
      kv[j] = __half2float(g_qkv[ib + D_ + lane*4 + j]);       ssk += kv[j]*kv[j];
      g_vh[vb + lane*4 + j] = g_qkv[ib + 2*D_ + lane*4 + j];
    }
    ssq = warpSum(ssq); ssk = warpSum(ssk);
    float aq = sK * sqrtf(ssq);
    float sq = (aq < 1e-6f) ? (1.0f + aq*aq/6.0f) : (sinhf(aq)/aq);
    float ak = sK * sqrtf(ssk);
    float sk = (ak < 1e-6f) ? (1.0f + ak*ak/6.0f) : (sinhf(ak)/ak);
#pragma unroll
    for (int j=0;j<4;j++){
      g_qh[qb + lane*4 + j] = __float2half(sq * qv[j]);
      g_kh[qb + lane*4 + j] = __float2half(sk * kv[j]);
    }
    float x0q = sqrtf(inv_negK + sq*sq*ssq);
    float x0k = sqrtf(inv_negK + sk*sk*ssk);
    g_qh[qb + 128 + lane] = (lane==0) ? __float2half(-x0q) : __float2half(0.f);
    g_kh[qb + 128 + lane] = (lane==0) ? __float2half( x0k) : __float2half(0.f);
  }
}

// causal-aware softmax
__global__ void softmaxk(){
  int q = blockIdx.x, z = blockIdx.y, t = threadIdx.x;
  size_t base = ((size_t)z*S_ + q)*S_;
  int nlim = (q & ~127) + 128;
  float v[8]; float mx = -3.0e38f;
#pragma unroll
  for (int j=0;j<8;j++){
    int c = t + j*256;
    bool ok = c < nlim;
    v[j] = ok ? __half2float(g_sc[base + c]) : -1.0e30f;
    mx = fmaxf(mx, v[j]);
  }
  mx = blockMax(mx);
  float s = 0.f;
#pragma unroll
  for (int j=0;j<8;j++){ v[j] = __expf(v[j] - mx); s += v[j]; }
  s = blockSum(s);
  float inv = 1.0f / s;
#pragma unroll
  for (int j=0;j<8;j++){
    int c = t + j*256;
    if (c < nlim) g_pm[base + c] = __float2half(v[j] * inv);
  }
}

// per-row: u1 = scale2 * u2 / rms(u2)
__global__ void prep2(const float* __restrict__ scale2){
  int row = blockIdx.x, t = threadIdx.x;
  float u[8]; float ss = 0.f;
#pragma unroll
  for (int j=0;j<8;j++){ u[j] = g_u2[(size_t)row*D_ + t + j*256]; ss += u[j]*u[j]; }
  ss = blockSum(ss);
  float rinv = 1.0f / sqrtf(ss*(1.0f/D_) + 1e-6f);
#pragma unroll
  for (int j=0;j<8;j++){
    int c = t + j*256;
    g_u1[(size_t)row*D_ + c] = __float2half(scale2[c] * u[j] * rinv);
  }
}

// per-row: out = exp_map(uf), K=-1
__global__ void finalk(float* __restrict__ out){
  int row = blockIdx.x, t = threadIdx.x;
  float u[8]; float ss = 0.f;
#pragma unroll
  for (int j=0;j<8;j++){ u[j] = g_uf[(size_t)row*D_ + t + j*256]; ss += u[j]*u[j]; }
  ss = blockSum(ss);
  float n = sqrtf(ss);
  float sinc = (n < 1e-6f) ? (1.0f + n*n/6.0f) : (sinhf(n)/n);
  float* o = out + (size_t)row*2049;
  if (t == 0) o[0] = sqrtf(1.0f + sinc*sinc*ss);
#pragma unroll
  for (int j=0;j<8;j++) o[1 + t + j*256] = sinc * u[j];
}

enum { M_HALF = 0, M_SCORES = 1, M_PV = 2, M_WO = 3, M_GELU = 4, M_W2 = 5 };

// ============ 4-warp 128x128 dense GEMM: C = A[M,K] @ Bt[N,K]^T ============
// 128 threads; warp grid 2x2, 64x64 per warp (16 accum frags -> high frag reuse).
template<int MODE>
__global__ __launch_bounds__(128) void gemm4w(
    const __half* __restrict__ A, const __half* __restrict__ Bt,
    void* __restrict__ C, const float* __restrict__ aux,
    int K, int ldc)
{
  extern __shared__ __half smem[];
  const int rm0 = blockIdx.y * 128;
  const int cn0 = blockIdx.x * 128;
  const int tid = threadIdx.x;
  const int wid = tid >> 5, lane = tid & 31;
  const int wm = wid >> 1, wn = wid & 1;       // 2x2 warp grid, 64x64 each
  const int KT = K >> 5;

  const int r0 = tid >> 2, c0 = (tid & 3) * 8;  // 4 its x 32 rows, 4 x 8-half chunks

  auto loadTile = [&](int kt, int buf){
    int k0 = kt << 5;
    __half* as = smem + buf*S4_STAGE_H;
    __half* bs = as + 5120;
#pragma unroll
    for (int it=0; it<4; it++){
      int r = r0 + it*32;
      cp16(&as[r*40 + c0], A  + (size_t)(rm0 + r)*K + k0 + c0);
      cp16(&bs[r*40 + c0], Bt + (size_t)(cn0 + r)*K + k0 + c0);
    }
  };

  wmma::fragment<wmma::accumulator,16,16,16,float> fc[4][4];
#pragma unroll
  for (int i=0;i<4;i++)
#pragma unroll
    for (int j=0;j<4;j++) wmma::fill_fragment(fc[i][j], 0.0f);

  loadTile(0, 0); cp_commit();
  if (KT > 1) loadTile(1, 1);
  cp_commit();

  for (int kt = 0; kt < KT; kt++){
    cp_wait<1>();
    __syncthreads();
    if (kt + 2 < KT) loadTile(kt+2, (kt+2)%3);
    cp_commit();
    const __half* as = smem + (kt%3)*S4_STAGE_H;
    const __half* bs = as + 5120;
#pragma unroll
    for (int kk=0; kk<32; kk+=16){
      wmma::fragment<wmma::matrix_a,16,16,16,__half,wmma::row_major> fa[4];
      wmma::fragment<wmma::matrix_b,16,16,16,__half,wmma::col_major> fb[4];
#pragma unroll
      for (int i=0;i<4;i++)
        wmma::load_matrix_sync(fa[i], &as[(wm*64 + i*16)*40 + kk], 40);
#pragma unroll
      for (int j=0;j<4;j++)
        wmma::load_matrix_sync(fb[j], &bs[(wn*64 + j*16)*40 + kk], 40);
#pragma unroll
      for (int i=0;i<4;i++)
#pragma unroll
        for (int j=0;j<4;j++)
          wmma::mma_sync(fc[i][j], fa[i], fb[j], fc[i][j]);
    }
  }

  // ---- epilogue: stage 16x16 tiles through shared, vectorized stores ----
  __syncthreads();
  float* Es = reinterpret_cast<float*>(smem);
  float* es = Es + wid*320;
  const int r  = lane >> 1;
  const int ch = (lane & 1) * 8;
#pragma unroll
  for (int mi=0; mi<4; mi++){
#pragma unroll
    for (int nj=0; nj<4; nj++){
      wmma::store_matrix_sync(es, fc[mi][nj], 20, wmma::mem_row_major);
      __syncwarp();
      float4 v0 = *reinterpret_cast<const float4*>(&es[r*20 + ch]);
      float4 v1 = *reinterpret_cast<const float4*>(&es[r*20 + ch + 4]);
      float vals[8] = {v0.x,v0.y,v0.z,v0.w, v1.x,v1.y,v1.z,v1.w};
      int gr = rm0 + wm*64 + mi*16 + r;
      int gc = cn0 + wn*64 + nj*16 + ch;
      if constexpr (MODE == M_HALF || MODE == M_GELU){
        __half h8[8];
#pragma unroll
        for (int e=0;e<8;e++){
          float val = vals[e];
          if constexpr (MODE == M_GELU)
            val = 0.5f*val*(1.0f + erff(val*0.70710678118654752f));
          h8[e] = __float2half(val);
        }
        *reinterpret_cast<int4*>((__half*)C + (size_t)gr*ldc + gc) = *reinterpret_cast<int4*>(h8);
      } else {  // M_WO / M_W2: fp32 out = val + aux
        size_t i2 = (size_t)gr*ldc + gc;
        float4 a0 = *reinterpret_cast<const float4*>(aux + i2);
        float4 a1 = *reinterpret_cast<const float4*>(aux + i2 + 4);
        float4 o0 = make_float4(vals[0]+a0.x, vals[1]+a0.y, vals[2]+a0.z, vals[3]+a0.w);
        float4 o1 = make_float4(vals[4]+a1.x, vals[5]+a1.y, vals[6]+a1.z, vals[7]+a1.w);
        *reinterpret_cast<float4*>((float*)C + i2)     = o0;
        *reinterpret_cast<float4*>((float*)C + i2 + 4) = o1;
      }
      __syncwarp();
    }
  }
}

// ---------------- wmma GEMM 128x128 8-warp (scores / PV) ----------------
template<int MODE>
__global__ __launch_bounds__(256) void gemm_k(
    const __half* __restrict__ A, const __half* __restrict__ Bm,
    void* __restrict__ C, const float* __restrict__ aux,
    int M, int N, int K, int lda, int ldb, int ldc,
    long long strA, long long strB, long long strC)
{
  constexpr bool BT = (MODE == M_SCORES);
  extern __shared__ __half smem[];
  __half* As = smem;
  __half* Bs = smem + NSTAGE*STAGE_H;

  const int z = blockIdx.z;
  const int rm0 = blockIdx.y * 128;
  const int cn0 = blockIdx.x * 128;

  if constexpr (MODE == M_SCORES){
    if (cn0 > rm0 + 127) return;
  }
  if constexpr (MODE == M_PV){
    K = min(K, rm0 + 128);
  }

  const __half* Ab = A  + (size_t)z * strA;
  const __half* Bb = Bm + (size_t)z * strB;
  const int tid = threadIdx.x;
  const int wid = tid >> 5, lane = tid & 31;
  const int wm = wid >> 1, wn = wid & 1;
  const int KT = K >> 5;

  const int ar0 = tid >> 2,  ac0 = (tid & 3) * 8;
  const int br0 = tid >> 4,  bc0 = (tid & 15) * 8;
  const int tr0 = tid >> 2,  tc0 = (tid & 3) * 8;

  auto loadTile = [&](int kt, int buf){
    int k0 = kt << 5;
    __half* as = As + buf*STAGE_H;
    __half* bs = Bs + buf*STAGE_H;
#pragma unroll
    for (int it=0; it<2; it++){
      int r = ar0 + it*64;
      cp16(&as[r*40 + ac0], Ab + (size_t)(rm0 + r)*lda + k0 + ac0);
    }
    if constexpr (!BT){
#pragma unroll
      for (int it=0; it<2; it++){
        int r = br0 + it*16;
        cp16(&bs[r*136 + bc0], Bb + (size_t)(k0 + r)*ldb + cn0 + bc0);
      }
    } else {
#pragma unroll
      for (int it=0; it<2; it++){
        int r = tr0 + it*64;
        cp16(&bs[r*40 + tc0], Bb + (size_t)(cn0 + r)*ldb + k0 + tc0);
      }
    }
  };

  wmma::fragment<wmma::accumulator,16,16,16,float> fc[2][4];
#pragma unroll
  for (int i=0;i<2;i++)
#pragma unroll
    for (int j=0;j<4;j++) wmma::fill_fragment(fc[i][j], 0.0f);

  loadTile(0, 0); cp_commit();
  if (KT > 1) loadTile(1, 1);
  cp_commit();

  for (int kt = 0; kt < KT; kt++){
    cp_wait<1>();
    __syncthreads();
    if (kt + 2 < KT) loadTile(kt+2, (kt+2)%3);
    cp_commit();
    const __half* as = As + (kt%3)*STAGE_H;
    const __half* bs = Bs + (kt%3)*STAGE_H;
#pragma unroll
    for (int kk=0; kk<32; kk+=16){
      wmma::fragment<wmma::matrix_a,16,16,16,__half,wmma::row_major> fa[2];
#pragma unroll
      for (int i=0;i<2;i++)
        wmma::load_matrix_sync(fa[i], &as[(wm*32 + i*16)*40 + kk], 40);
      if constexpr (!BT){
#pragma unroll
        for (int j=0;j<4;j++){
          wmma::fragment<wmma::matrix_b,16,16,16,__half,wmma::row_major> fb;
          wmma::load_matrix_sync(fb, &bs[kk*136 + wn*64 + j*16], 136);
#pragma unroll
          for (int i=0;i<2;i++) wmma::mma_sync(fc[i][j], fa[i], fb, fc[i][j]);
        }
      } else {
#pragma unroll
        for (int j=0;j<4;j++){
          wmma::fragment<wmma::matrix_b,16,16,16,__half,wmma::col_major> fb;
          wmma::load_matrix_sync(fb, &bs[(wn*64 + j*16)*40 + kk], 40);
#pragma unroll
          for (int i=0;i<2;i++) wmma::mma_sync(fc[i][j], fa[i], fb, fc[i][j]);
        }
      }
    }
  }

  __syncthreads();
  float* Es = reinterpret_cast<float*>(smem);
  float* es = Es + wid*320;
  const int r  = lane >> 1;
  const int ch = (lane & 1) * 8;
#pragma unroll
  for (int mi=0; mi<2; mi++){
#pragma unroll
    for (int nj=0; nj<4; nj++){
      wmma::store_matrix_sync(es, fc[mi][nj], 20, wmma::mem_row_major);
      __syncwarp();
      float4 v0 = *reinterpret_cast<const float4*>(&es[r*20 + ch]);
      float4 v1 = *reinterpret_cast<const float4*>(&es[r*20 + ch + 4]);
      float vals[8] = {v0.x,v0.y,v0.z,v0.w, v1.x,v1.y,v1.z,v1.w};
      int gr = rm0 + wm*32 + mi*16 + r;
      int gc = cn0 + wn*64 + nj*16 + ch;
      if constexpr (MODE == M_SCORES){
        __half h8[8];
#pragma unroll
        for (int e=0;e<8;e++){
          float val = vals[e] * 0.17677669529663687f;
          if (gc + e > gr) val = -60000.0f;
          h8[e] = __float2half(val);
        }
        *reinterpret_cast<int4*>((__half*)C + (size_t)z*strC + (size_t)gr*ldc + gc) = *reinterpret_cast<int4*>(h8);
      } else if constexpr (MODE == M_PV){
        int b = z >> 4, h = z & 15;
        __half h8[8];
#pragma unroll
        for (int e=0;e<8;e++) h8[e] = __float2half(vals[e]);
        *reinterpret_cast<int4*>((__half*)C + ((size_t)(b*S_ + gr))*D_ + (size_t)h*DH_ + gc) = *reinterpret_cast<int4*>(h8);
      }
      __syncwarp();
    }
  }
}

// ---------------- host ----------------
static void* symaddr(const void* s){
  void* p = nullptr;
  cudaGetSymbolAddress(&p, s);
  return p;
}

extern "C" void kernel_launch(void* const* d_in, const int* in_sizes, int n_in,
                              void* d_out, int out_size) {
  const float* x      = (const float*)d_in[0];
  const float* scale1 = (const float*)d_in[2];
  const float* scale2 = (const float*)d_in[3];
  const float* Wq     = (const float*)d_in[4];
  const float* Wk     = (const float*)d_in[5];
  const float* Wv     = (const float*)d_in[6];
  const float* Wo     = (const float*)d_in[7];
  const float* headK  = (const float*)d_in[8];
  const float* W1     = (const float*)d_in[9];
  const float* W2     = (const float*)d_in[10];

  __half* wqkv = (__half*)symaddr(g_wqkv);
  __half* wo = (__half*)symaddr(g_wo);
  __half* w1 = (__half*)symaddr(g_w1);
  __half* w2 = (__half*)symaddr(g_w2);
  __half* u1 = (__half*)symaddr(g_u1);
  __half* qh = (__half*)symaddr(g_qh);
  __half* kh = (__half*)symaddr(g_kh);
  __half* vh = (__half*)symaddr(g_vh);
  __half* pm = (__half*)symaddr(g_pm);
  __half* ao = (__half*)symaddr(g_ao);
  __half* hid= (__half*)symaddr(g_hid);
  void*   qkv= symaddr(g_qkv);
  void*   sc = symaddr(g_sc);
  void*   u2 = symaddr(g_u2);
  void*   uf = symaddr(g_uf);
  const float* vlog = (const float*)symaddr(g_v);

  cudaFuncSetAttribute(gemm_k<M_SCORES>, cudaFuncAttributeMaxDynamicSharedMemorySize, SMEM_BYTES);
  cudaFuncSetAttribute(gemm_k<M_PV>,     cudaFuncAttributeMaxDynamicSharedMemorySize, SMEM_BYTES);
  cudaFuncSetAttribute(gemm4w<M_HALF>,   cudaFuncAttributeMaxDynamicSharedMemorySize, S4_SMEM);
  cudaFuncSetAttribute(gemm4w<M_WO>,     cudaFuncAttributeMaxDynamicSharedMemorySize, S4_SMEM);
  cudaFuncSetAttribute(gemm4w<M_GELU>,   cudaFuncAttributeMaxDynamicSharedMemorySize, S4_SMEM);
  cudaFuncSetAttribute(gemm4w<M_W2>,     cudaFuncAttributeMaxDynamicSharedMemorySize, S4_SMEM);

  // 1) weight transpose + convert: W [K,N] fp32 -> Wt [N,K] fp16 (QKV packed)
  f2hT<<<dim3(D_/32,  D_/32),  256>>>(Wq, wqkv,                        D_,   D_);
  f2hT<<<dim3(D_/32,  D_/32),  256>>>(Wk, wqkv + (size_t)D_*D_,        D_,   D_);
  f2hT<<<dim3(D_/32,  D_/32),  256>>>(Wv, wqkv + (size_t)2*D_*D_,      D_,   D_);
  f2hT<<<dim3(D_/32,  D_/32),  256>>>(Wo, wo, D_,   D_);
  f2hT<<<dim3(DFF_/32,D_/32),  256>>>(W1, w1, D_,   DFF_);
  f2hT<<<dim3(D_/32,  DFF_/32),256>>>(W2, w2, DFF_, D_);

  // 2) log map + rmsnorm-in-log-space
  prep1<<<NROWS,256>>>(x, scale1);

  // 3) fused QKV projection (one GEMM, N=6144)
  gemm4w<M_HALF><<<dim3(DQKV/128, NROWS/128), 128, S4_SMEM>>>(u1, wqkv, qkv, nullptr, D_, DQKV);

  // 4) lorentz lift
  headprep<<<NROWS,256>>>(headK);

  // 5) scores (wmma 128x128, masked tiles skipped)
  gemm_k<M_SCORES><<<dim3(16,16,BH_),256,SMEM_BYTES>>>(qh, kh, sc, nullptr,
      S_, S_, DHP_, DHP_, DHP_, S_,
      (long long)S_*DHP_, (long long)S_*DHP_, (long long)S_*S_);

  // 6) softmax
  softmaxk<<<dim3(S_,BH_),256>>>();

  // 7) P @ V (wmma 128x128, causal K cap)
  gemm_k<M_PV><<<dim3(1,16,BH_),256,SMEM_BYTES>>>(pm, vh, ao, nullptr,
      S_, DH_, S_, S_, DH_, DH_,
      (long long)S_*S_, (long long)S_*DH_, 0);

  // 8) attn @ Wo + residual(v) -> u2
  gemm4w<M_WO><<<dim3(D_/128, NROWS/128), 128, S4_SMEM>>>(ao, wo, u2, vlog, D_, D_);

  // 9) rmsnorm in log space
  prep2<<<NROWS,256>>>(scale2);

  // 10) FFN up + GELU
  gemm4w<M_GELU><<<dim3(DFF_/128, NROWS/128), 128, S4_SMEM>>>(u1, w1, hid, nullptr, D_, DFF_);

  // 11) FFN down + residual(u2) -> uf
  gemm4w<M_W2><<<dim3(D_/128, NROWS/128), 128, S4_SMEM>>>(hid, w2, uf, (const float*)u2, DFF_, D_);

  // 12) final exp map
  finalk<<<NROWS,256>>>((float*)d_out);
}

// round 9
// speedup vs baseline: 1.1739x; 1.0923x over previous
#include <cuda_runtime.h>
#include <cuda_fp16.h>
#include <cstdint>
#include <mma.h>
using namespace nvcuda;

// Problem dims (fixed by the dataset)
#define B_    2
#define S_    2048
#define D_    2048
#define H_    16
#define DH_   128
#define DFF_  8192
#define DHP_  144           // 129-dim lorentz q/k padded to 144 (9 k16 steps)
#define BH_   32            // B_*H_
#define NROWS 4096          // B_*S_
#define DQKV  6144          // 3*D_

// 4-warp 128x128 dense path: per stage A(128x32,str40) + B(128x32,str40)
#define S4_STAGE_H 10240                         // halves per stage
#define S4_SMEM    (3 * S4_STAGE_H * 2)          // 61440 B

// fused attention smem (halves): Q(128x152) + 2x K(128x152) + 2x V(128x136)
#define AQ_STR   152
#define AV_STR   136
#define AQ_H     (128*AQ_STR)     // 19456 halves per Q/K tile
#define AV_H     (128*AV_STR)     // 17408 halves per V tile
#define AKS_OFF  AQ_H
#define AVS_OFF  (3*AQ_H)
#define ATT_SMEM ((3*AQ_H + 2*AV_H) * 2)         // 186368 B

// ---------------- scratch (static device globals; no allocs) ----------------
__device__ float  g_v  [(size_t)NROWS*D_];
__device__ __half g_u1 [(size_t)NROWS*D_];
__device__ __half g_wqkv[(size_t)DQKV*D_];   // packed transposed [6144,2048] fp16
__device__ __half g_wo [(size_t)D_*D_];
__device__ __half g_w1 [(size_t)D_*DFF_];
__device__ __half g_w2 [(size_t)DFF_*D_];
__device__ __half g_qkv[(size_t)NROWS*DQKV]; // packed QKV output [row, 6144]
__device__ __half g_qh [(size_t)BH_*S_*DHP_];
__device__ __half g_kh [(size_t)BH_*S_*DHP_];
__device__ __half g_vh [(size_t)BH_*S_*DH_];
__device__ __half g_ao [(size_t)NROWS*D_];
__device__ float  g_u2 [(size_t)NROWS*D_];
__device__ __half g_hid[(size_t)NROWS*DFF_];
__device__ float  g_uf [(size_t)NROWS*D_];

// ---------------- PTX helpers ----------------
__device__ __forceinline__ uint32_t smem_u32(const void* p){
  uint32_t a;
  asm("{ .reg .u64 t; cvta.to.shared.u64 t, %1; cvt.u32.u64 %0, t; }" : "=r"(a) : "l"(p));
  return a;
}
__device__ __forceinline__ void cp16(void* dst, const void* src){
  unsigned d = (unsigned)__cvta_generic_to_shared(dst);
  asm volatile("cp.async.cg.shared.global [%0], [%1], 16;" :: "r"(d), "l"(src));
}
__device__ __forceinline__ void cp_commit(){ asm volatile("cp.async.commit_group;"); }
template<int N> __device__ __forceinline__ void cp_wait(){
  asm volatile("cp.async.wait_group %0;" :: "n"(N));
}
__device__ __forceinline__ void ldsm4(uint32_t& r0, uint32_t& r1, uint32_t& r2, uint32_t& r3, uint32_t a){
  asm volatile("ldmatrix.sync.aligned.m8n8.x4.shared.b16 {%0,%1,%2,%3}, [%4];"
               : "=r"(r0), "=r"(r1), "=r"(r2), "=r"(r3) : "r"(a));
}
__device__ __forceinline__ void ldsm4t(uint32_t& r0, uint32_t& r1, uint32_t& r2, uint32_t& r3, uint32_t a){
  asm volatile("ldmatrix.sync.aligned.m8n8.x4.trans.shared.b16 {%0,%1,%2,%3}, [%4];"
               : "=r"(r0), "=r"(r1), "=r"(r2), "=r"(r3) : "r"(a));
}
__device__ __forceinline__ void mma16816(float* c, uint32_t a0, uint32_t a1, uint32_t a2, uint32_t a3,
                                         uint32_t b0, uint32_t b1){
  asm volatile(
    "mma.sync.aligned.m16n8k16.row.col.f32.f16.f16.f32 "
    "{%0,%1,%2,%3}, {%4,%5,%6,%7}, {%8,%9}, {%0,%1,%2,%3};"
    : "+f"(c[0]), "+f"(c[1]), "+f"(c[2]), "+f"(c[3])
    : "r"(a0), "r"(a1), "r"(a2), "r"(a3), "r"(b0), "r"(b1));
}
__device__ __forceinline__ uint32_t packh2(float a, float b){
  __half2 h = __floats2half2_rn(a, b);
  return *reinterpret_cast<uint32_t*>(&h);
}

// ---------------- reductions ----------------
__device__ __forceinline__ float warpSum(float v){
#pragma unroll
  for (int o=16;o>0;o>>=1) v += __shfl_xor_sync(0xffffffffu, v, o);
  return v;
}
__device__ float blockSum(float v){
  __shared__ float sh[9];
  int lane = threadIdx.x & 31, wid = threadIdx.x >> 5;
  v = warpSum(v);
  __syncthreads();
  if (lane == 0) sh[wid] = v;
  __syncthreads();
  if (wid == 0){
    float r = (lane < 8) ? sh[lane] : 0.f;
    r = warpSum(r);
    if (lane == 0) sh[8] = r;
  }
  __syncthreads();
  return sh[8];
}

// ---------------- small kernels ----------------
// fused transpose + fp32->fp16: src [K,N] -> dst [N,K]
__global__ void f2hT(const float* __restrict__ src, __half* __restrict__ dst, int K, int N){
  __shared__ float tile[32][33];
  int k0 = blockIdx.y*32, n0 = blockIdx.x*32;
  int tx = threadIdx.x & 31, ty = threadIdx.x >> 5;
#pragma unroll
  for (int i=0;i<32;i+=8)
    tile[ty+i][tx] = src[(size_t)(k0+ty+i)*N + n0+tx];
  __syncthreads();
#pragma unroll
  for (int i=0;i<32;i+=8)
    dst[(size_t)(n0+ty+i)*K + k0+tx] = __float2half(tile[tx][ty+i]);
}

// per-row: v = log_map(x); u1 = scale1 * v / rms(v)
__global__ void prep1(const float* __restrict__ x, const float* __restrict__ scale1){
  int row = blockIdx.x, t = threadIdx.x;
  const float* xr = x + (size_t)row*2049 + 1;
  float xi[8]; float ss = 0.f;
#pragma unroll
  for (int j=0;j<8;j++){ xi[j] = xr[t + j*256]; ss += xi[j]*xi[j]; }
  ss = blockSum(ss);
  float n = sqrtf(ss);
  float f = (n < 1e-6f) ? (1.0f - n*n/6.0f) : (asinhf(n) / fmaxf(n, 1e-12f));
  float rinv = 1.0f / sqrtf(f*f*ss*(1.0f/D_) + 1e-6f);
#pragma unroll
  for (int j=0;j<8;j++){
    int c = t + j*256;
    float v = f * xi[j];
    g_v [(size_t)row*D_ + c] = v;
    g_u1[(size_t)row*D_ + c] = __float2half(scale1[c] * v * rinv);
  }
}

// per (b,s): lift q,k to lorentz (129 dims in 144), copy v head-major
__global__ void headprep(const float* __restrict__ headK){
  int r = blockIdx.x;
  int b = r >> 11, s = r & 2047;
  int wid = threadIdx.x >> 5, lane = threadIdx.x & 31;
#pragma unroll
  for (int rep=0; rep<2; rep++){
    int h = wid*2 + rep;
    int z = b*H_ + h;
    size_t ib = (size_t)r*DQKV + (size_t)h*DH_;
    size_t qb = ((size_t)z*S_ + s)*DHP_;
    size_t vb = ((size_t)z*S_ + s)*DH_;
    float Kh = headK[h];
    float sK = sqrtf(-Kh);
    float inv_negK = -1.0f / Kh;
    float qv[4], kv[4]; float ssq = 0.f, ssk = 0.f;
#pragma unroll
    for (int j=0;j<4;j++){
      qv[j] = __half2float(g_qkv[ib + lane*4 + j]);            ssq += qv[j]*qv[j];
      kv[j] = __half2float(g_qkv[ib + D_ + lane*4 + j]);       ssk += kv[j]*kv[j];
      g_vh[vb + lane*4 + j] = g_qkv[ib + 2*D_ + lane*4 + j];
    }
    ssq = warpSum(ssq); ssk = warpSum(ssk);
    float aq = sK * sqrtf(ssq);
    float sq = (aq < 1e-6f) ? (1.0f + aq*aq/6.0f) : (sinhf(aq)/aq);
    float ak = sK * sqrtf(ssk);
    float sk = (ak < 1e-6f) ? (1.0f + ak*ak/6.0f) : (sinhf(ak)/ak);
#pragma unroll
    for (int j=0;j<4;j++){
      g_qh[qb + lane*4 + j] = __float2half(sq * qv[j]);
      g_kh[qb + lane*4 + j] = __float2half(sk * kv[j]);
    }
    float x0q = sqrtf(inv_negK + sq*sq*ssq);
    float x0k = sqrtf(inv_negK + sk*sk*ssk);
    if (lane < 16){
      g_qh[qb + 128 + lane] = (lane==0) ? __float2half(-x0q) : __float2half(0.f);
      g_kh[qb + 128 + lane] = (lane==0) ? __float2half( x0k) : __float2half(0.f);
    }
  }
}

// per-row: u1 = scale2 * u2 / rms(u2)
__global__ void prep2(const float* __restrict__ scale2){
  int row = blockIdx.x, t = threadIdx.x;
  float u[8]; float ss = 0.f;
#pragma unroll
  for (int j=0;j<8;j++){ u[j] = g_u2[(size_t)row*D_ + t + j*256]; ss += u[j]*u[j]; }
  ss = blockSum(ss);
  float rinv = 1.0f / sqrtf(ss*(1.0f/D_) + 1e-6f);
#pragma unroll
  for (int j=0;j<8;j++){
    int c = t + j*256;
    g_u1[(size_t)row*D_ + c] = __float2half(scale2[c] * u[j] * rinv);
  }
}

// per-row: out = exp_map(uf), K=-1
__global__ void finalk(float* __restrict__ out){
  int row = blockIdx.x, t = threadIdx.x;
  float u[8]; float ss = 0.f;
#pragma unroll
  for (int j=0;j<8;j++){ u[j] = g_uf[(size_t)row*D_ + t + j*256]; ss += u[j]*u[j]; }
  ss = blockSum(ss);
  float n = sqrtf(ss);
  float sinc = (n < 1e-6f) ? (1.0f + n*n/6.0f) : (sinhf(n)/n);
  float* o = out + (size_t)row*2049;
  if (t == 0) o[0] = sqrtf(1.0f + sinc*sinc*ss);
#pragma unroll
  for (int j=0;j<8;j++) o[1 + t + j*256] = sinc * u[j];
}

// ============ fused flash attention (causal) ============
// grid (16, 32): x -> q-tile (reversed for longest-first), y -> z = b*16+h
// 8 warps; warp w owns q rows [w*16, w*16+16). Online softmax, O in regs.
__global__ __launch_bounds__(256, 1) void fused_attn(){
  extern __shared__ __half smem[];
  const int qt = 15 - blockIdx.x;
  const int z  = blockIdx.y;
  const int b  = z >> 4, h = z & 15;
  const int tid = threadIdx.x, w = tid >> 5, lane = tid & 31;
  const uint32_t sb = smem_u32(smem);

  const __half* Qg = g_qh + ((size_t)z*S_ + (size_t)qt*128)*DHP_;

  // load Q (128 x 144, smem stride 152)
#pragma unroll
  for (int i=0;i<9;i++){
    int idx = tid + i*256;              // 2304 chunks
    int row = idx/18, cc = idx%18;
    cp16(&smem[row*AQ_STR + cc*8], Qg + (size_t)row*DHP_ + cc*8);
  }
  // load K/V tile 0 into buf 0
  {
    const __half* Kg = g_kh + ((size_t)z*S_)*DHP_;
    const __half* Vg = g_vh + ((size_t)z*S_)*DH_;
#pragma unroll
    for (int i=0;i<9;i++){
      int idx = tid + i*256;
      int row = idx/18, cc = idx%18;
      cp16(&smem[AKS_OFF + row*AQ_STR + cc*8], Kg + (size_t)row*DHP_ + cc*8);
    }
#pragma unroll
    for (int i=0;i<8;i++){
      int idx = tid + i*256;
      int row = idx >> 4, cc = idx & 15;
      cp16(&smem[AVS_OFF + row*AV_STR + cc*8], Vg + (size_t)row*DH_ + cc*8);
    }
  }
  cp_commit();

  float Ofr[16][4];
#pragma unroll
  for (int i=0;i<16;i++){ Ofr[i][0]=0.f; Ofr[i][1]=0.f; Ofr[i][2]=0.f; Ofr[i][3]=0.f; }
  float m0 = -1e30f, m1 = -1e30f, l0 = 0.f, l1 = 0.f;

  // ldmatrix lane address components
  const uint32_t qa_row = w*16 + (lane&7) + ((lane>>3)&1)*8;
  const uint32_t qa_col = (lane>>4)*8;
  const uint32_t kb_row = (lane&7) + ((lane>>4)&1)*8;   // n offset
  const uint32_t kb_col = ((lane>>3)&1)*8;              // k offset
  const uint32_t vb_row = (lane&7) + ((lane>>3)&1)*8;   // k offset
  const uint32_t vb_col = ((lane>>4)&1)*8;              // n offset
  const int rl0 = w*16 + (lane>>2);                     // local q row (c0,c1)
  const float SCALE = 0.17677669529663687f;             // 2/sqrt(128)

  for (int j = 0; j <= qt; j++){
    const int buf = j & 1;
    cp_wait<0>();
    __syncthreads();
    // prefetch next K/V into other buffer (overlaps compute below)
    if (j + 1 <= qt){
      const int nb = buf ^ 1;
      const __half* Kg = g_kh + ((size_t)z*S_ + (size_t)(j+1)*128)*DHP_;
      const __half* Vg = g_vh + ((size_t)z*S_ + (size_t)(j+1)*128)*DH_;
#pragma unroll
      for (int i=0;i<9;i++){
        int idx = tid + i*256;
        int row = idx/18, cc = idx%18;
        cp16(&smem[AKS_OFF + nb*AQ_H + row*AQ_STR + cc*8], Kg + (size_t)row*DHP_ + cc*8);
      }
#pragma unroll
      for (int i=0;i<8;i++){
        int idx = tid + i*256;
        int row = idx >> 4, cc = idx & 15;
        cp16(&smem[AVS_OFF + nb*AV_H + row*AV_STR + cc*8], Vg + (size_t)row*DH_ + cc*8);
      }
      cp_commit();
    }

    // ---- S = Q @ K^T  (128 rows x 128 kv), warp strip 16 x 128 ----
    float Sv[16][4];
#pragma unroll
    for (int i=0;i<16;i++){ Sv[i][0]=0.f; Sv[i][1]=0.f; Sv[i][2]=0.f; Sv[i][3]=0.f; }
    const uint32_t Kb = sb + (AKS_OFF + buf*AQ_H)*2;
#pragma unroll
    for (int ks=0; ks<9; ks++){
      uint32_t a0,a1,a2,a3;
      ldsm4(a0,a1,a2,a3, sb + (qa_row*AQ_STR + ks*16 + qa_col)*2);
#pragma unroll
      for (int jp=0; jp<8; jp++){
        uint32_t b0,b1,b2,b3;
        ldsm4(b0,b1,b2,b3, Kb + ((jp*16 + kb_row)*AQ_STR + ks*16 + kb_col)*2);
        mma16816(Sv[2*jp],   a0,a1,a2,a3, b0,b1);
        mma16816(Sv[2*jp+1], a0,a1,a2,a3, b2,b3);
      }
    }

    // ---- scale + causal mask (diagonal tile only) ----
#pragma unroll
    for (int i=0;i<16;i++){
      Sv[i][0]*=SCALE; Sv[i][1]*=SCALE; Sv[i][2]*=SCALE; Sv[i][3]*=SCALE;
    }
    if (j == qt){
      const int cbase = (lane&3)*2;
#pragma unroll
      for (int jp=0; jp<16; jp++){
        int c0 = jp*8 + cbase, c1 = c0 + 1;
        if (c0 > rl0)   Sv[jp][0] = -1e30f;
        if (c1 > rl0)   Sv[jp][1] = -1e30f;
        if (c0 > rl0+8) Sv[jp][2] = -1e30f;
        if (c1 > rl0+8) Sv[jp][3] = -1e30f;
      }
    }

    // ---- online softmax update ----
    float mx0 = -1e30f, mx1 = -1e30f;
#pragma unroll
    for (int i=0;i<16;i++){
      mx0 = fmaxf(mx0, fmaxf(Sv[i][0], Sv[i][1]));
      mx1 = fmaxf(mx1, fmaxf(Sv[i][2], Sv[i][3]));
    }
    mx0 = fmaxf(mx0, __shfl_xor_sync(0xffffffffu, mx0, 1));
    mx0 = fmaxf(mx0, __shfl_xor_sync(0xffffffffu, mx0, 2));
    mx1 = fmaxf(mx1, __shfl_xor_sync(0xffffffffu, mx1, 1));
    mx1 = fmaxf(mx1, __shfl_xor_sync(0xffffffffu, mx1, 2));
    float m0n = fmaxf(m0, mx0), m1n = fmaxf(m1, mx1);
    float al0 = __expf(m0 - m0n), al1 = __expf(m1 - m1n);
    float s0 = 0.f, s1 = 0.f;
#pragma unroll
    for (int i=0;i<16;i++){
      Sv[i][0] = __expf(Sv[i][0] - m0n);
      Sv[i][1] = __expf(Sv[i][1] - m0n);
      Sv[i][2] = __expf(Sv[i][2] - m1n);
      Sv[i][3] = __expf(Sv[i][3] - m1n);
      s0 += Sv[i][0] + Sv[i][1];
      s1 += Sv[i][2] + Sv[i][3];
    }
    s0 += __shfl_xor_sync(0xffffffffu, s0, 1);
    s0 += __shfl_xor_sync(0xffffffffu, s0, 2);
    s1 += __shfl_xor_sync(0xffffffffu, s1, 1);
    s1 += __shfl_xor_sync(0xffffffffu, s1, 2);
    l0 = l0*al0 + s0; l1 = l1*al1 + s1;
    m0 = m0n; m1 = m1n;
#pragma unroll
    for (int i=0;i<16;i++){
      Ofr[i][0]*=al0; Ofr[i][1]*=al0; Ofr[i][2]*=al1; Ofr[i][3]*=al1;
    }

    // ---- O += P @ V ----
    const uint32_t Vb = sb + (AVS_OFF + buf*AV_H)*2;
#pragma unroll
    for (int kc=0; kc<8; kc++){
      uint32_t a0 = packh2(Sv[2*kc][0],   Sv[2*kc][1]);
      uint32_t a1 = packh2(Sv[2*kc][2],   Sv[2*kc][3]);
      uint32_t a2 = packh2(Sv[2*kc+1][0], Sv[2*kc+1][1]);
      uint32_t a3 = packh2(Sv[2*kc+1][2], Sv[2*kc+1][3]);
#pragma unroll
      for (int np=0; np<8; np++){
        uint32_t b0,b1,b2,b3;
        ldsm4t(b0,b1,b2,b3, Vb + ((kc*16 + vb_row)*AV_STR + np*16 + vb_col)*2);
        mma16816(Ofr[2*np],   a0,a1,a2,a3, b0,b1);
        mma16816(Ofr[2*np+1], a0,a1,a2,a3, b2,b3);
      }
    }
  }

  // ---- epilogue: normalize, stage through smem (reuse K buf), store ----
  __syncthreads();
  __half* stage = smem + AKS_OFF;       // 128 x 136 half
  float r0i = 1.f/l0, r1i = 1.f/l1;
  const int cb = (lane&3)*2;
#pragma unroll
  for (int np=0; np<16; np++){
    *reinterpret_cast<__half2*>(&stage[rl0*AV_STR + np*8 + cb]) =
        __floats2half2_rn(Ofr[np][0]*r0i, Ofr[np][1]*r0i);
    *reinterpret_cast<__half2*>(&stage[(rl0+8)*AV_STR + np*8 + cb]) =
        __floats2half2_rn(Ofr[np][2]*r1i, Ofr[np][3]*r1i);
  }
  __syncthreads();
#pragma unroll
  for (int i=0;i<8;i++){
    int idx = tid + i*256;
    int row = idx >> 4, cc = idx & 15;
    *reinterpret_cast<int4*>(&g_ao[((size_t)(b*S_ + qt*128 + row))*D_ + h*DH_ + cc*8]) =
        *reinterpret_cast<const int4*>(&stage[row*AV_STR + cc*8]);
  }
}

enum { M_HALF = 0, M_WO = 3, M_GELU = 4, M_W2 = 5 };

// ============ 4-warp 128x128 dense GEMM: C = A[M,K] @ Bt[N,K]^T ============
template<int MODE>
__global__ __launch_bounds__(128) void gemm4w(
    const __half* __restrict__ A, const __half* __restrict__ Bt,
    void* __restrict__ C, const float* __restrict__ aux,
    int K, int ldc)
{
  extern __shared__ __half smem[];
  const int rm0 = blockIdx.y * 128;
  const int cn0 = blockIdx.x * 128;
  const int tid = threadIdx.x;
  const int wid = tid >> 5, lane = tid & 31;
  const int wm = wid >> 1, wn = wid & 1;
  const int KT = K >> 5;

  const int r0 = tid >> 2, c0 = (tid & 3) * 8;

  auto loadTile = [&](int kt, int buf){
    int k0 = kt << 5;
    __half* as = smem + buf*S4_STAGE_H;
    __half* bs = as + 5120;
#pragma unroll
    for (int it=0; it<4; it++){
      int r = r0 + it*32;
      cp16(&as[r*40 + c0], A  + (size_t)(rm0 + r)*K + k0 + c0);
      cp16(&bs[r*40 + c0], Bt + (size_t)(cn0 + r)*K + k0 + c0);
    }
  };

  wmma::fragment<wmma::accumulator,16,16,16,float> fc[4][4];
#pragma unroll
  for (int i=0;i<4;i++)
#pragma unroll
    for (int j=0;j<4;j++) wmma::fill_fragment(fc[i][j], 0.0f);

  loadTile(0, 0); cp_commit();
  if (KT > 1) loadTile(1, 1);
  cp_commit();

  for (int kt = 0; kt < KT; kt++){
    cp_wait<1>();
    __syncthreads();
    if (kt + 2 < KT) loadTile(kt+2, (kt+2)%3);
    cp_commit();
    const __half* as = smem + (kt%3)*S4_STAGE_H;
    const __half* bs = as + 5120;
#pragma unroll
    for (int kk=0; kk<32; kk+=16){
      wmma::fragment<wmma::matrix_a,16,16,16,__half,wmma::row_major> fa[4];
      wmma::fragment<wmma::matrix_b,16,16,16,__half,wmma::col_major> fb[4];
#pragma unroll
      for (int i=0;i<4;i++)
        wmma::load_matrix_sync(fa[i], &as[(wm*64 + i*16)*40 + kk], 40);
#pragma unroll
      for (int j=0;j<4;j++)
        wmma::load_matrix_sync(fb[j], &bs[(wn*64 + j*16)*40 + kk], 40);
#pragma unroll
      for (int i=0;i<4;i++)
#pragma unroll
        for (int j=0;j<4;j++)
          wmma::mma_sync(fc[i][j], fa[i], fb[j], fc[i][j]);
    }
  }

  __syncthreads();
  float* Es = reinterpret_cast<float*>(smem);
  float* es = Es + wid*320;
  const int r  = lane >> 1;
  const int ch = (lane & 1) * 8;
#pragma unroll
  for (int mi=0; mi<4; mi++){
#pragma unroll
    for (int nj=0; nj<4; nj++){
      wmma::store_matrix_sync(es, fc[mi][nj], 20, wmma::mem_row_major);
      __syncwarp();
      float4 v0 = *reinterpret_cast<const float4*>(&es[r*20 + ch]);
      float4 v1 = *reinterpret_cast<const float4*>(&es[r*20 + ch + 4]);
      float vals[8] = {v0.x,v0.y,v0.z,v0.w, v1.x,v1.y,v1.z,v1.w};
      int gr = rm0 + wm*64 + mi*16 + r;
      int gc = cn0 + wn*64 + nj*16 + ch;
      if constexpr (MODE == M_HALF || MODE == M_GELU){
        __half h8[8];
#pragma unroll
        for (int e=0;e<8;e++){
          float val = vals[e];
          if constexpr (MODE == M_GELU)
            val = 0.5f*val*(1.0f + erff(val*0.70710678118654752f));
          h8[e] = __float2half(val);
        }
        *reinterpret_cast<int4*>((__half*)C + (size_t)gr*ldc + gc) = *reinterpret_cast<int4*>(h8);
      } else {
        size_t i2 = (size_t)gr*ldc + gc;
        float4 a0 = *reinterpret_cast<const float4*>(aux + i2);
        float4 a1 = *reinterpret_cast<const float4*>(aux + i2 + 4);
        float4 o0 = make_float4(vals[0]+a0.x, vals[1]+a0.y, vals[2]+a0.z, vals[3]+a0.w);
        float4 o1 = make_float4(vals[4]+a1.x, vals[5]+a1.y, vals[6]+a1.z, vals[7]+a1.w);
        *reinterpret_cast<float4*>((float*)C + i2)     = o0;
        *reinterpret_cast<float4*>((float*)C + i2 + 4) = o1;
      }
      __syncwarp();
    }
  }
}

// ---------------- host ----------------
static void* symaddr(const void* s){
  void* p = nullptr;
  cudaGetSymbolAddress(&p, s);
  return p;
}

extern "C" void kernel_launch(void* const* d_in, const int* in_sizes, int n_in,
                              void* d_out, int out_size) {
  const float* x      = (const float*)d_in[0];
  const float* scale1 = (const float*)d_in[2];
  const float* scale2 = (const float*)d_in[3];
  const float* Wq     = (const float*)d_in[4];
  const float* Wk     = (const float*)d_in[5];
  const float* Wv     = (const float*)d_in[6];
  const float* Wo     = (const float*)d_in[7];
  const float* headK  = (const float*)d_in[8];
  const float* W1     = (const float*)d_in[9];
  const float* W2     = (const float*)d_in[10];

  __half* wqkv = (__half*)symaddr(g_wqkv);
  __half* wo = (__half*)symaddr(g_wo);
  __half* w1 = (__half*)symaddr(g_w1);
  __half* w2 = (__half*)symaddr(g_w2);
  __half* u1 = (__half*)symaddr(g_u1);
  __half* ao = (__half*)symaddr(g_ao);
  __half* hid= (__half*)symaddr(g_hid);
  void*   qkv= symaddr(g_qkv);
  void*   u2 = symaddr(g_u2);
  void*   uf = symaddr(g_uf);
  const float* vlog = (const float*)symaddr(g_v);

  cudaFuncSetAttribute(gemm4w<M_HALF>,   cudaFuncAttributeMaxDynamicSharedMemorySize, S4_SMEM);
  cudaFuncSetAttribute(gemm4w<M_WO>,     cudaFuncAttributeMaxDynamicSharedMemorySize, S4_SMEM);
  cudaFuncSetAttribute(gemm4w<M_GELU>,   cudaFuncAttributeMaxDynamicSharedMemorySize, S4_SMEM);
  cudaFuncSetAttribute(gemm4w<M_W2>,     cudaFuncAttributeMaxDynamicSharedMemorySize, S4_SMEM);
  cudaFuncSetAttribute(fused_attn,       cudaFuncAttributeMaxDynamicSharedMemorySize, ATT_SMEM);

  // 1) weight transpose + convert
  f2hT<<<dim3(D_/32,  D_/32),  256>>>(Wq, wqkv,                   D_,   D_);
  f2hT<<<dim3(D_/32,  D_/32),  256>>>(Wk, wqkv + (size_t)D_*D_,   D_,   D_);
  f2hT<<<dim3(D_/32,  D_/32),  256>>>(Wv, wqkv + (size_t)2*D_*D_, D_,   D_);
  f2hT<<<dim3(D_/32,  D_/32),  256>>>(Wo, wo, D_,   D_);
  f2hT<<<dim3(DFF_/32,D_/32),  256>>>(W1, w1, D_,   DFF_);
  f2hT<<<dim3(D_/32,  DFF_/32),256>>>(W2, w2, DFF_, D_);

  // 2) log map + rmsnorm-in-log-space
  prep1<<<NROWS,256>>>(x, scale1);

  // 3) fused QKV projection
  gemm4w<M_HALF><<<dim3(DQKV/128, NROWS/128), 128, S4_SMEM>>>(u1, wqkv, qkv, nullptr, D_, DQKV);

  // 4) lorentz lift
  headprep<<<NROWS,256>>>(headK);

  // 5) fused flash attention (scores + softmax + PV)
  fused_attn<<<dim3(16,32), 256, ATT_SMEM>>>();

  // 6) attn @ Wo + residual(v) -> u2
  gemm4w<M_WO><<<dim3(D_/128, NROWS/128), 128, S4_SMEM>>>(ao, wo, u2, vlog, D_, D_);

  // 7) rmsnorm in log space
  prep2<<<NROWS,256>>>(scale2);

  // 8) FFN up + GELU
  gemm4w<M_GELU><<<dim3(DFF_/128, NROWS/128), 128, S4_SMEM>>>(u1, w1, hid, nullptr, D_, DFF_);

  // 9) FFN down + residual(u2) -> uf
  gemm4w<M_W2><<<dim3(D_/128, NROWS/128), 128, S4_SMEM>>>(hid, w2, uf, (const float*)u2, DFF_, D_);

  // 10) final exp map
  finalk<<<NROWS,256>>>((float*)d_out);
}